// round 1
// baseline (speedup 1.0000x reference)
#include <cuda_runtime.h>
#include <cuda_bf16.h>

// DSPA fused:  out = x1 + x4, where
//   x2 = dilated conv1d(x1)            [2,64,4094]
//   d[n,j] = <Q[n], K'[j]> (128-dim), P = sigmoid(d)   (softmax over batch of 2!)
//   O[n,c2] = sum_j P[n,j] * V[c2,j]
//   out[0,c,n] = x1[0,c,n] + O[n,c]
//   out[1,c,n] = x1[1,c,n] + S1[c] - O[n,64+c]
//
// All fp32. f32x2 packed FMA in both GEMMs, packing the reduction dim so no
// operand duplication is needed.

#define NJ 4096      // padded j extent (true 4094, rows 4094/4095 zero in V)
#define NC 128       // stacked channel dim (2*64)
#define NN 4096      // n extent

// scratch (no cudaMalloc allowed)
__device__ __align__(256) float g_K[NJ * NC];   // K'[j][c2]
__device__ __align__(256) float g_V[NC * NJ];   // V[c2][j]  (natural conv layout)
__device__ __align__(256) float g_S1[64];

__device__ __forceinline__ unsigned long long dfma2(unsigned long long a,
                                                    unsigned long long b,
                                                    unsigned long long c) {
    unsigned long long r;
    asm("fma.rn.f32x2 %0, %1, %2, %3;" : "=l"(r) : "l"(a), "l"(b), "l"(c));
    return r;
}
__device__ __forceinline__ float pairsum(unsigned long long v) {
    float lo, hi;
    asm("mov.b64 {%0, %1}, %2;" : "=f"(lo), "=f"(hi) : "l"(v));
    return lo + hi;
}

// ---------------------------------------------------------------------------
// Kernel 1: dilated conv -> writes K' (transposed, sign-flipped) and V (natural)
// grid 128 (32 j per block), block 128 (c2 = b*64+co)
// ---------------------------------------------------------------------------
#define CONV_SMEM_FLOATS (64 * 195 + 128 * 36)
__global__ void __launch_bounds__(128) conv_kernel(const float* __restrict__ x,
                                                   const float* __restrict__ w,
                                                   const float* __restrict__ bias) {
    extern __shared__ float sm[];
    float* ws  = sm;             // [64][195]  (padded: 195 % 32 = 3, conflict-free)
    float* x1s = sm + 64 * 195;  // [128][36]

    const int tid = threadIdx.x;
    const int j0 = blockIdx.x * 32;

    for (int f = tid; f < 64 * 64 * 3; f += 128) {
        int co = f / 192, rem = f % 192;
        ws[co * 195 + rem] = w[f];
    }
    for (int f = tid; f < 128 * 36; f += 128) {
        int row = f / 36, p = f % 36;
        int pos = j0 - 1 + p;
        x1s[row * 36 + p] = (pos >= 0 && pos < NN) ? x[row * NN + pos] : 0.0f;
    }
    __syncthreads();

    const int c2 = tid;
    const int bb = c2 >> 6, co = c2 & 63;
    float acc[32];
    float bv = bias[co];
#pragma unroll
    for (int jj = 0; jj < 32; jj++) acc[jj] = bv;

    for (int ci = 0; ci < 64; ci++) {
        float w0 = ws[co * 195 + ci * 3 + 0];
        float w1 = ws[co * 195 + ci * 3 + 1];
        float w2 = ws[co * 195 + ci * 3 + 2];
        const float* xr = &x1s[(bb * 64 + ci) * 36];
#pragma unroll
        for (int jj = 0; jj < 32; jj++)
            acc[jj] += w0 * xr[jj] + w1 * xr[jj + 2] + w2 * xr[jj + 4];
    }

#pragma unroll 4
    for (int jj = 0; jj < 32; jj++) {
        int j = j0 + jj;
        float v = (j < 4094) ? acc[jj] : 0.0f;   // zero-pad tail rows
        g_V[c2 * NJ + j] = v;
        g_K[j * NC + c2] = (c2 < 64) ? v : -v;
    }
}

// ---------------------------------------------------------------------------
// Kernel 2: S1[c] = sum_j V[64+c][j]   (deterministic tree reduce)
// ---------------------------------------------------------------------------
__global__ void __launch_bounds__(256) s1_kernel() {
    __shared__ float red[256];
    const int c = blockIdx.x;
    float s = 0.0f;
    for (int j = threadIdx.x; j < 4094; j += 256) s += g_V[(64 + c) * NJ + j];
    red[threadIdx.x] = s;
    __syncthreads();
    for (int st = 128; st > 0; st >>= 1) {
        if (threadIdx.x < st) red[threadIdx.x] += red[threadIdx.x + st];
        __syncthreads();
    }
    if (threadIdx.x == 0) g_S1[c] = red[0];
}

// ---------------------------------------------------------------------------
// Kernel 3: main fused attention-like kernel.
// grid 128 (TN=32 n-rows each), block 256.  TJ=128 per j-tile, 32 tiles.
// smem (floats): Qs[32][132] | Ks[128][132] | Vs[128][132] | Ps[32][132]
// (stride 132: 132%32==4 -> LDS.128 phases of 8 lanes hit distinct banks;
//  row starts are 16B aligned)
// Osm reuses Ks region in epilogue.
// ---------------------------------------------------------------------------
#define QS_OFF 0
#define KS_OFF 4224
#define VS_OFF 21120
#define PS_OFF 38016
#define MAIN_SMEM_FLOATS 42240

__global__ void __launch_bounds__(256, 1) dspa_main_kernel(const float* __restrict__ x,
                                                           float* __restrict__ out) {
    extern __shared__ float sm[];
    float* Qs = sm + QS_OFF;
    float* Ks = sm + KS_OFF;
    float* Vs = sm + VS_OFF;
    float* Ps = sm + PS_OFF;

    const int tid = threadIdx.x;
    const int tx = tid & 63;   // j / c dim
    const int ty = tid >> 6;   // n dim (0..3); warp has fixed ty -> Q/P loads broadcast
    const int n0 = blockIdx.x * 32;

    // load Q tile [32 n][128 c2] from x (x is [c2][n] contiguous)
#pragma unroll
    for (int r = 0; r < 16; r++) {
        int f = tid + 256 * r;          // 0..4095
        int c2 = f >> 5, n = f & 31;
        Qs[n * 132 + c2] = x[c2 * NN + n0 + n];
    }

    unsigned long long Oacc[8][2];
#pragma unroll
    for (int ii = 0; ii < 8; ii++) { Oacc[ii][0] = 0ull; Oacc[ii][1] = 0ull; }

    for (int jt = 0; jt < 32; jt++) {
        __syncthreads();   // prior GEMM2 done with Vs/Ps before overwrite
        // load K' tile [128 j][128 c2] and V tile [128 c][128 j]
        const float4* K4 = reinterpret_cast<const float4*>(g_K);
        const float4* V4 = reinterpret_cast<const float4*>(g_V);
#pragma unroll
        for (int r = 0; r < 16; r++) {
            int f = tid + 256 * r;       // 0..4095
            int row = f >> 5, c4 = f & 31;
            float4 kv = K4[(jt * 128 + row) * 32 + c4];
            *reinterpret_cast<float4*>(&Ks[row * 132 + 4 * c4]) = kv;
            float4 vv = V4[row * (NJ / 4) + jt * 32 + c4];
            *reinterpret_cast<float4*>(&Vs[row * 132 + 4 * c4]) = vv;
        }
        __syncthreads();

        // ---- GEMM1: d[n][j] over c2=128, f32x2 packed over c2-pairs ----
        unsigned long long acc[8][2];
#pragma unroll
        for (int ii = 0; ii < 8; ii++) { acc[ii][0] = 0ull; acc[ii][1] = 0ull; }

#pragma unroll 4
        for (int k4 = 0; k4 < 32; k4++) {
            ulonglong2 kA = *reinterpret_cast<const ulonglong2*>(&Ks[tx * 132 + 4 * k4]);
            ulonglong2 kB = *reinterpret_cast<const ulonglong2*>(&Ks[(tx + 64) * 132 + 4 * k4]);
#pragma unroll
            for (int ii = 0; ii < 8; ii++) {
                ulonglong2 q = *reinterpret_cast<const ulonglong2*>(&Qs[(ty + 4 * ii) * 132 + 4 * k4]);
                acc[ii][0] = dfma2(q.x, kA.x, acc[ii][0]);
                acc[ii][0] = dfma2(q.y, kA.y, acc[ii][0]);
                acc[ii][1] = dfma2(q.x, kB.x, acc[ii][1]);
                acc[ii][1] = dfma2(q.y, kB.y, acc[ii][1]);
            }
        }
        // sigmoid + store P[n][j]
#pragma unroll
        for (int ii = 0; ii < 8; ii++) {
#pragma unroll
            for (int jj = 0; jj < 2; jj++) {
                float d = pairsum(acc[ii][jj]);
                float p = __fdividef(1.0f, 1.0f + __expf(-d));
                Ps[(ty + 4 * ii) * 132 + tx + 64 * jj] = p;
            }
        }
        __syncthreads();

        // ---- GEMM2: O[n][c] += P[n][j] * V[c][j], f32x2 packed over j-pairs ----
#pragma unroll 4
        for (int j4 = 0; j4 < 32; j4++) {
            ulonglong2 vA = *reinterpret_cast<const ulonglong2*>(&Vs[tx * 132 + 4 * j4]);
            ulonglong2 vB = *reinterpret_cast<const ulonglong2*>(&Vs[(tx + 64) * 132 + 4 * j4]);
#pragma unroll
            for (int ii = 0; ii < 8; ii++) {
                ulonglong2 p = *reinterpret_cast<const ulonglong2*>(&Ps[(ty + 4 * ii) * 132 + 4 * j4]);
                Oacc[ii][0] = dfma2(p.x, vA.x, Oacc[ii][0]);
                Oacc[ii][0] = dfma2(p.y, vA.y, Oacc[ii][0]);
                Oacc[ii][1] = dfma2(p.x, vB.x, Oacc[ii][1]);
                Oacc[ii][1] = dfma2(p.y, vB.y, Oacc[ii][1]);
            }
        }
    }

    // ---- epilogue: stage O to smem (transpose), then coalesced writeback ----
    __syncthreads();
    float* Osm = Ks;   // [128][33], 4224 floats, fits in Ks region
#pragma unroll
    for (int ii = 0; ii < 8; ii++) {
#pragma unroll
        for (int cc = 0; cc < 2; cc++) {
            Osm[(tx + 64 * cc) * 33 + (ty + 4 * ii)] = pairsum(Oacc[ii][cc]);
        }
    }
    __syncthreads();

    const int wrp = tid >> 5, lane = tid & 31;
#pragma unroll 4
    for (int rr = 0; rr < 16; rr++) {
        int c2 = wrp * 16 + rr;
        float o = Osm[c2 * 33 + lane];
        float xv = x[c2 * NN + n0 + lane];
        float val = (c2 < 64) ? (xv + o) : (xv + g_S1[c2 - 64] - o);
        out[c2 * NN + n0 + lane] = val;
    }
}

// ---------------------------------------------------------------------------
extern "C" void kernel_launch(void* const* d_in, const int* in_sizes, int n_in,
                              void* d_out, int out_size) {
    const float* x  = (const float*)d_in[0];   // [2,64,16,16,16] = [128][4096]
    const float* cw = (const float*)d_in[1];   // [64,64,3]
    const float* cb = (const float*)d_in[2];   // [64]
    float* out = (float*)d_out;

    const int conv_smem = CONV_SMEM_FLOATS * sizeof(float);   // ~68 KB
    const int main_smem = MAIN_SMEM_FLOATS * sizeof(float);   // ~165 KB
    cudaFuncSetAttribute(conv_kernel, cudaFuncAttributeMaxDynamicSharedMemorySize, conv_smem);
    cudaFuncSetAttribute(dspa_main_kernel, cudaFuncAttributeMaxDynamicSharedMemorySize, main_smem);

    conv_kernel<<<128, 128, conv_smem>>>(x, cw, cb);
    s1_kernel<<<64, 256>>>();
    dspa_main_kernel<<<128, 256, main_smem>>>(x, out);
}

// round 4
// speedup vs baseline: 2.9039x; 2.9039x over previous
#include <cuda_runtime.h>
#include <cstdint>

// ============================================================================
// DSPA via mma.sync tf32 (legal on generic compute_103 target, runs on tensor pipe):
//   x2 = dilated conv1d(x1); softmax over batch(2) => P = sigmoid(d),
//   d[n,j] = <Q[n], K'[j]>_128,  O[n,c2] = sum_j P[n,j] V[c2,j]
//   out[0,c,n] = x1 + O[n,c];  out[1,c,n] = x1 + S1[c] - O[n,64+c]
// ============================================================================

#define NN 4096
#define NC 128
#define NJ 4096
#define NSPLIT 8
#define JRANGE 512
#define JSTEP 64
#define NSTEPS 8

__device__ __align__(256) float g_Kt[NJ * NC];          // K'[j][c2] (tf32-rounded)
__device__ __align__(256) float g_V[NC * NJ];           // V[c2][j]  (tf32-rounded)
__device__ __align__(256) float g_Q[NN * NC];           // Q[n][c2]  (tf32-rounded)
__device__ __align__(256) float g_Op[NSPLIT * NC * NN]; // partial O [s][c2][n]
__device__ float g_S1[64];

// ---------------------------------------------------------------- helpers
__device__ __forceinline__ float tf32r(float x) {
    uint32_t r;
    asm("cvt.rna.tf32.f32 %0, %1;" : "=r"(r) : "f"(x));
    return __uint_as_float(r);
}
__device__ __forceinline__ float sigf(float x) {
    return __fdividef(1.0f, 1.0f + __expf(-x));
}
__device__ __forceinline__ void mma8(float* d, const uint32_t* a, const uint32_t* b) {
    asm volatile(
        "mma.sync.aligned.m16n8k8.row.col.f32.tf32.tf32.f32 "
        "{%0,%1,%2,%3}, {%4,%5,%6,%7}, {%8,%9}, {%0,%1,%2,%3};"
        : "+f"(d[0]), "+f"(d[1]), "+f"(d[2]), "+f"(d[3])
        : "r"(a[0]), "r"(a[1]), "r"(a[2]), "r"(a[3]), "r"(b[0]), "r"(b[1]));
}

// ---------------------------------------------------------------------------
// Kernel 1: dilated conv -> K' (transposed, sign-flipped, j-padded) and V
// grid 128 (32 j per block), block 512 (c2 = tid&127, j-group = tid>>7)
// ---------------------------------------------------------------------------
#define CONV_SMEM_BYTES ((64 * 195 + 128 * 37) * 4)
__global__ void __launch_bounds__(512) conv_kernel(const float* __restrict__ x,
                                                   const float* __restrict__ w,
                                                   const float* __restrict__ bias) {
    extern __shared__ float sm[];
    float* ws  = sm;             // [64][195]
    float* x1s = sm + 64 * 195;  // [128][37] (36 used)

    const int tid = threadIdx.x;
    const int j0 = blockIdx.x * 32;

    for (int f = tid; f < 64 * 64 * 3; f += 512) {
        int co = f / 192, rem = f % 192;
        ws[co * 195 + rem] = w[f];
    }
    for (int f = tid; f < 128 * 36; f += 512) {
        int row = f / 36, p = f % 36;
        int pos = j0 - 1 + p;
        x1s[row * 37 + p] = (pos >= 0 && pos < NN) ? x[row * NN + pos] : 0.0f;
    }
    __syncthreads();

    const int c2 = tid & 127;
    const int grp = tid >> 7;          // 0..3, 8 j each
    const int bb = c2 >> 6, co = c2 & 63;
    const int base = grp * 8;
    float acc[8];
    float bv = bias[co];
#pragma unroll
    for (int jj = 0; jj < 8; jj++) acc[jj] = bv;

    for (int ci = 0; ci < 64; ci++) {
        float w0 = ws[co * 195 + ci * 3 + 0];
        float w1 = ws[co * 195 + ci * 3 + 1];
        float w2 = ws[co * 195 + ci * 3 + 2];
        const float* xr = &x1s[(bb * 64 + ci) * 37 + base];
#pragma unroll
        for (int jj = 0; jj < 8; jj++)
            acc[jj] += w0 * xr[jj] + w1 * xr[jj + 2] + w2 * xr[jj + 4];
    }

#pragma unroll
    for (int jj = 0; jj < 8; jj++) {
        int j = j0 + base + jj;
        float v = (j < 4094) ? tf32r(acc[jj]) : 0.0f;   // tf32-round, zero-pad tail
        g_V[c2 * NJ + j] = v;
        g_Kt[j * NC + c2] = (c2 < 64) ? v : -v;
    }
}

// ---------------------------------------------------------------------------
// Kernel 2: S1[c] = sum_j V[64+c][j] over the SAME rounded V used in GEMM2
// ---------------------------------------------------------------------------
__global__ void __launch_bounds__(256) s1_kernel() {
    __shared__ float red[256];
    const int c = blockIdx.x;
    float s = 0.0f;
    for (int j = threadIdx.x; j < 4094; j += 256) s += g_V[(64 + c) * NJ + j];
    red[threadIdx.x] = s;
    __syncthreads();
    for (int st = 128; st > 0; st >>= 1) {
        if (threadIdx.x < st) red[threadIdx.x] += red[threadIdx.x + st];
        __syncthreads();
    }
    if (threadIdx.x == 0) g_S1[c] = red[0];
}

// ---------------------------------------------------------------------------
// Kernel 3: transpose x [c2][n] -> g_Q [n][c2], tf32-rounded
// ---------------------------------------------------------------------------
__global__ void transpose_kernel(const float* __restrict__ x) {
    __shared__ float t[32][33];
    int n0 = blockIdx.x * 32, c0 = blockIdx.y * 32;
    int tx = threadIdx.x, ty = threadIdx.y;  // 32 x 8
#pragma unroll
    for (int k = 0; k < 4; k++)
        t[ty + 8 * k][tx] = tf32r(x[(c0 + ty + 8 * k) * NN + n0 + tx]);
    __syncthreads();
#pragma unroll
    for (int k = 0; k < 4; k++)
        g_Q[(n0 + ty + 8 * k) * NC + c0 + tx] = t[tx][ty + 8 * k];
}

// ---------------------------------------------------------------------------
// Kernel 4: main flash-style kernel on mma.sync tf32.
// grid 256 = 32 m-tiles(128 n) x 8 j-splits(512 j), block 256 (8 warps).
// Warp grid: wm = warp&3 (32 n-rows), wn = warp>>2 (32 j-cols G1 / 64 c2-cols G2)
// SMEM floats: Qs[128][132] | Ks[64][132] | Vs[128][68] | Ps[128][68]
//   (pad 4: fragment lds hits 32 distinct banks: bank = 4*(row&7)+(col&3))
// ---------------------------------------------------------------------------
#define QS_F 0
#define KS_F 16896
#define VS_F 25344
#define PS_F 34048
#define TOT_F 42752
#define MAIN_SMEM_BYTES (TOT_F * 4)

__global__ void __launch_bounds__(256, 1) dspa_main_kernel() {
    extern __shared__ float sm[];
    float* Qs = sm + QS_F;
    float* Ks = sm + KS_F;
    float* Vs = sm + VS_F;
    float* Ps = sm + PS_F;

    const int tid = threadIdx.x;
    const int warp = tid >> 5, lane = tid & 31;
    const int g = lane >> 2, t = lane & 3;
    const int wm = (warp & 3) * 32;
    const int wn1 = (warp >> 2) * 32;
    const int wn2 = (warp >> 2) * 64;
    const int m0 = (blockIdx.x & 31) << 7;
    const int split = blockIdx.x >> 5;
    const int jb0 = split * JRANGE;

    // stage Q tile [128][128] (float4, padded stride 132)
#pragma unroll
    for (int it = 0; it < 16; it++) {
        int idx = it * 256 + tid;          // 0..4095 float4 chunks
        int r = idx >> 5, q = idx & 31;
        float4 v = *reinterpret_cast<const float4*>(&g_Q[(m0 + r) * NC + 4 * q]);
        *reinterpret_cast<float4*>(&Qs[r * 132 + 4 * q]) = v;
    }

    float acc2[16][4];
#pragma unroll
    for (int i = 0; i < 16; i++)
#pragma unroll
        for (int k = 0; k < 4; k++) acc2[i][k] = 0.0f;

    for (int s = 0; s < NSTEPS; s++) {
        const int jb = jb0 + s * JSTEP;
        __syncthreads();   // prev iter's GEMM1/GEMM2 done reading Ks/Vs/Ps (+Q staged, s=0)
        // stage K [64 j][128 c2] and V [128 c2][64 j]
#pragma unroll
        for (int it = 0; it < 8; it++) {
            int idx = it * 256 + tid;      // 0..2047
            {
                int r = idx >> 5, q = idx & 31;
                float4 v = *reinterpret_cast<const float4*>(&g_Kt[(jb + r) * NC + 4 * q]);
                *reinterpret_cast<float4*>(&Ks[r * 132 + 4 * q]) = v;
            }
            {
                int r = idx >> 4, q = idx & 15;
                float4 v = *reinterpret_cast<const float4*>(&g_V[r * NJ + jb + 4 * q]);
                *reinterpret_cast<float4*>(&Vs[r * 68 + 4 * q]) = v;
            }
        }
        __syncthreads();

        // ---- GEMM1: d[128n x 64j] = Q x K'^T over c2=128 ----
        float acc1[8][4];
#pragma unroll
        for (int i = 0; i < 8; i++)
#pragma unroll
            for (int k = 0; k < 4; k++) acc1[i][k] = 0.0f;

#pragma unroll
        for (int k0 = 0; k0 < 128; k0 += 8) {
            uint32_t a[2][4], b[4][2];
#pragma unroll
            for (int mt = 0; mt < 2; mt++) {
                const float* q0 = &Qs[(wm + mt * 16 + g) * 132 + k0 + t];
                a[mt][0] = __float_as_uint(q0[0]);
                a[mt][2] = __float_as_uint(q0[4]);
                const float* q1 = q0 + 8 * 132;
                a[mt][1] = __float_as_uint(q1[0]);
                a[mt][3] = __float_as_uint(q1[4]);
            }
#pragma unroll
            for (int nt = 0; nt < 4; nt++) {
                const float* kp = &Ks[(wn1 + nt * 8 + g) * 132 + k0 + t];
                b[nt][0] = __float_as_uint(kp[0]);
                b[nt][1] = __float_as_uint(kp[4]);
            }
#pragma unroll
            for (int mt = 0; mt < 2; mt++)
#pragma unroll
                for (int nt = 0; nt < 4; nt++)
                    mma8(acc1[mt * 4 + nt], a[mt], b[nt]);
        }

        // sigmoid + store P (tf32-rounded) at fragment positions
#pragma unroll
        for (int mt = 0; mt < 2; mt++)
#pragma unroll
            for (int nt = 0; nt < 4; nt++) {
                int rn = wm + mt * 16 + g;
                int cj = wn1 + nt * 8 + 2 * t;
                const float* c = acc1[mt * 4 + nt];
                Ps[rn * 68 + cj]           = tf32r(sigf(c[0]));
                Ps[rn * 68 + cj + 1]       = tf32r(sigf(c[1]));
                Ps[(rn + 8) * 68 + cj]     = tf32r(sigf(c[2]));
                Ps[(rn + 8) * 68 + cj + 1] = tf32r(sigf(c[3]));
            }
        __syncthreads();

        // ---- GEMM2: O[128n x 128c2] += P x V^T over j=64 ----
#pragma unroll
        for (int k0 = 0; k0 < 64; k0 += 8) {
            uint32_t a[2][4], b[8][2];
#pragma unroll
            for (int mt = 0; mt < 2; mt++) {
                const float* p0 = &Ps[(wm + mt * 16 + g) * 68 + k0 + t];
                a[mt][0] = __float_as_uint(p0[0]);
                a[mt][2] = __float_as_uint(p0[4]);
                const float* p1 = p0 + 8 * 68;
                a[mt][1] = __float_as_uint(p1[0]);
                a[mt][3] = __float_as_uint(p1[4]);
            }
#pragma unroll
            for (int nt = 0; nt < 8; nt++) {
                const float* vp = &Vs[(wn2 + nt * 8 + g) * 68 + k0 + t];
                b[nt][0] = __float_as_uint(vp[0]);
                b[nt][1] = __float_as_uint(vp[4]);
            }
#pragma unroll
            for (int mt = 0; mt < 2; mt++)
#pragma unroll
                for (int nt = 0; nt < 8; nt++)
                    mma8(acc2[mt * 8 + nt], a[mt], b[nt]);
        }
    }

    // ---- epilogue: fragments -> smem [c2][n] -> coalesced partial writeback ----
    __syncthreads();
    float* Osm = sm;   // [128][129] floats = 66KB, reuses Qs/Ks space
#pragma unroll
    for (int mt = 0; mt < 2; mt++)
#pragma unroll
        for (int nt = 0; nt < 8; nt++) {
            int n = wm + mt * 16 + g;
            int c2 = wn2 + nt * 8 + 2 * t;
            const float* c = acc2[mt * 8 + nt];
            Osm[c2 * 129 + n]           = c[0];
            Osm[(c2 + 1) * 129 + n]     = c[1];
            Osm[c2 * 129 + n + 8]       = c[2];
            Osm[(c2 + 1) * 129 + n + 8] = c[3];
        }
    __syncthreads();
#pragma unroll
    for (int it = 0; it < 16; it++) {
        int idx = it * 256 + tid;
        int r = idx >> 5, q = idx & 31;
        float4 v = make_float4(Osm[r * 129 + 4 * q], Osm[r * 129 + 4 * q + 1],
                               Osm[r * 129 + 4 * q + 2], Osm[r * 129 + 4 * q + 3]);
        *reinterpret_cast<float4*>(&g_Op[((split << 7) + r) * NN + m0 + 4 * q]) = v;
    }
}

// ---------------------------------------------------------------------------
// Kernel 5: combine partials + residual + S1 -> out [c2][n]
// ---------------------------------------------------------------------------
__global__ void __launch_bounds__(256) reduce_kernel(const float* __restrict__ x,
                                                     float* __restrict__ out) {
    int idx = blockIdx.x * 256 + threadIdx.x;   // float4 units, 0..131071
    int c2 = idx >> 10;
    const float4* x4 = reinterpret_cast<const float4*>(x);
    const float4* o4 = reinterpret_cast<const float4*>(g_Op);
    float4 xv = x4[idx];
    float4 s = make_float4(0.f, 0.f, 0.f, 0.f);
#pragma unroll
    for (int sp = 0; sp < NSPLIT; sp++) {
        float4 v = o4[((sp << 7) + c2) * (NN / 4) + (idx & 1023)];
        s.x += v.x; s.y += v.y; s.z += v.z; s.w += v.w;
    }
    float4 r;
    if (c2 < 64) {
        r.x = xv.x + s.x; r.y = xv.y + s.y; r.z = xv.z + s.z; r.w = xv.w + s.w;
    } else {
        float b = g_S1[c2 - 64];
        r.x = xv.x + b - s.x; r.y = xv.y + b - s.y;
        r.z = xv.z + b - s.z; r.w = xv.w + b - s.w;
    }
    reinterpret_cast<float4*>(out)[idx] = r;
}

// ---------------------------------------------------------------------------
extern "C" void kernel_launch(void* const* d_in, const int* in_sizes, int n_in,
                              void* d_out, int out_size) {
    const float* x  = (const float*)d_in[0];   // [2,64,16,16,16] = [128][4096]
    const float* cw = (const float*)d_in[1];   // [64,64,3]
    const float* cb = (const float*)d_in[2];   // [64]
    float* out = (float*)d_out;

    cudaFuncSetAttribute(conv_kernel, cudaFuncAttributeMaxDynamicSharedMemorySize, CONV_SMEM_BYTES);
    cudaFuncSetAttribute(dspa_main_kernel, cudaFuncAttributeMaxDynamicSharedMemorySize, MAIN_SMEM_BYTES);

    conv_kernel<<<128, 512, CONV_SMEM_BYTES>>>(x, cw, cb);
    s1_kernel<<<64, 256>>>();
    transpose_kernel<<<dim3(128, 4), dim3(32, 8)>>>(x);
    dspa_main_kernel<<<256, 256, MAIN_SMEM_BYTES>>>();
    reduce_kernel<<<512, 256>>>(x, out);
}